// round 11
// baseline (speedup 1.0000x reference)
#include <cuda_runtime.h>
#include <cuda_bf16.h>
#include <cstdint>

// Problem constants
constexpr int Bc  = 2;
constexpr int Lc  = 2048;
constexpr int Dc  = 768;
constexpr int Hc  = 12;
constexpr int HDc = 64;
constexpr int BH  = Bc * Hc;            // 24
constexpr int Mrows = Bc * Lc;          // 4096

// Scratch (device globals; no allocation allowed)
__device__ __align__(128) float g_q[(size_t)BH * Lc * HDc];   // [b,h,l,d] tf32 (post-RoPE)
__device__ __align__(128) float g_k[(size_t)BH * Lc * HDc];
__device__ __align__(128) float g_v[(size_t)BH * Lc * HDc];
__device__ __align__(128) float g_o[(size_t)Bc * Lc * Dc];    // [b,l,h*64+d] tf32
__device__ __align__(128) float g_hid_tf[(size_t)Mrows * Dc];
__device__ __align__(128) float g_w_tf[(size_t)3 * Dc * Dc];
__device__ __align__(128) float g_wo_tf[(size_t)Dc * Dc];

// Fast SiLU: ex2.approx + rcp.approx (rel err ~1e-7, flag-independent).
__device__ __forceinline__ float silu_fast(float x) {
    float e, r;
    asm("ex2.approx.f32 %0, %1;" : "=f"(e) : "f"(-x * 1.4426950408889634f));
    asm("rcp.approx.f32 %0, %1;" : "=f"(r) : "f"(1.0f + e));
    return x * r;
}

__device__ __forceinline__ uint32_t f2tf(float x) {
    uint32_t r;
    asm("cvt.rna.tf32.f32 %0, %1;" : "=r"(r) : "f"(x));
    return r;
}

__device__ __forceinline__ uint32_t s2u(const void* p) {
    return (uint32_t)__cvta_generic_to_shared(p);
}

__device__ __forceinline__ void lm4(uint32_t& r0, uint32_t& r1,
                                    uint32_t& r2, uint32_t& r3, uint32_t addr) {
    asm volatile("ldmatrix.sync.aligned.m8n8.x4.shared.b16 {%0,%1,%2,%3},[%4];"
                 : "=r"(r0), "=r"(r1), "=r"(r2), "=r"(r3) : "r"(addr));
}

__device__ __forceinline__ void mma_tf32(float c[4],
                                         uint32_t a0, uint32_t a1, uint32_t a2, uint32_t a3,
                                         uint32_t b0, uint32_t b1) {
    asm volatile(
        "mma.sync.aligned.m16n8k8.row.col.f32.tf32.tf32.f32 "
        "{%0,%1,%2,%3},{%4,%5,%6,%7},{%8,%9},{%0,%1,%2,%3};"
        : "+f"(c[0]), "+f"(c[1]), "+f"(c[2]), "+f"(c[3])
        : "r"(a0), "r"(a1), "r"(a2), "r"(a3), "r"(b0), "r"(b1));
}

__device__ __forceinline__ void cpa16(uint32_t s, const void* g) {
    asm volatile("cp.async.cg.shared.global [%0], [%1], 16;" :: "r"(s), "l"(g));
}

// ---------------------------------------------------------------------------
// Kernel 0: single fused tf32-rounding pass over hidden + 4 weights.
// ---------------------------------------------------------------------------
constexpr int HID4 = Mrows * Dc / 4;    // 786432
constexpr int W4   = Dc * Dc / 4;       // 147456
constexpr int CVT_TOT = HID4 + 4 * W4;  // 1376256

__global__ void cvt_all_kernel(const float4* __restrict__ hid,
                               const float4* __restrict__ wq,
                               const float4* __restrict__ wk,
                               const float4* __restrict__ wv,
                               const float4* __restrict__ wo) {
    const int i = blockIdx.x * blockDim.x + threadIdx.x;
    if (i >= CVT_TOT) return;
    const float4* src;
    float4* dst;
    int off;
    if (i < HID4) {
        src = hid; dst = (float4*)g_hid_tf; off = i;
    } else {
        const int j = i - HID4;
        const int w = j / W4;
        off = j - w * W4;
        src = (w == 0) ? wq : (w == 1) ? wk : (w == 2) ? wv : wo;
        dst = (w < 3) ? (float4*)g_w_tf + (size_t)w * W4 : (float4*)g_wo_tf;
    }
    float4 v = src[off];
    float4 r;
    r.x = __uint_as_float(f2tf(v.x));
    r.y = __uint_as_float(f2tf(v.y));
    r.z = __uint_as_float(f2tf(v.z));
    r.w = __uint_as_float(f2tf(v.w));
    dst[off] = r;
}

// ---------------------------------------------------------------------------
// Kernel 1: tf32 GEMM, C[M,N] = A[M,768] * B[N,768]^T, inputs pre-rounded.
// CTA tile 128xBN, BK=32, warp tile 32x64, 4m x (BN/64)n warps.
// MODE 1 (BN=256): A=hid, B=Wq|Wk|Wv; epilogue SiLU (+fused RoPE for q/k).
// MODE 0 (BN=192): A=g_o, B=Wo; 128-CTA single wave on oproj.
// ---------------------------------------------------------------------------
constexpr int GLD = 36;                        // smem row pitch (floats), 144B
constexpr int gemm_smem(int BN) { return 2 * (128 + BN) * GLD * 4; }

template<int MODE, int BN>
__global__ __launch_bounds__(128 * (BN / 64), 1)
void gemm_tf32_kernel(float* __restrict__ Cout,
                      const float* __restrict__ cosp,
                      const float* __restrict__ sinp) {
    constexpr int NTH = 128 * (BN / 64);        // threads
    constexpr int NWN = BN / 64;                // warps in n
    extern __shared__ uint32_t sm[];
    uint32_t* As = sm;                          // [2][128*GLD]
    uint32_t* Bs = sm + 2 * 128 * GLD;          // [2][BN*GLD]

    const int tid = threadIdx.x;
    const int warp = tid >> 5, lane = tid & 31;
    const int gr = lane >> 2, gc = lane & 3;
    const int m0 = blockIdx.y * 128;
    const int n0g = blockIdx.x * BN;

    const float* Arow = ((MODE == 1) ? g_hid_tf : g_o) + (size_t)m0 * Dc;
    const float* Brow = ((MODE == 1) ? g_w_tf : g_wo_tf) + (size_t)n0g * Dc;

    const int warp_m0 = (warp / NWN) * 32;
    const int warp_n0 = (warp % NWN) * 64;

    const uint32_t laneA = ((lane & 15) * GLD + 4 * (lane >> 4)) * 4;
    const uint32_t laneB = ((((lane >> 3) & 1) * 8 + (lane & 7)) * GLD) * 4
                         + (lane >> 4) * 16;
    const uint32_t AsU = s2u(As), BsU = s2u(Bs);

    auto load_tile = [&](int kt, int buf) {
        uint32_t Ab = AsU + buf * 128 * GLD * 4;
        uint32_t Bb = BsU + buf * BN * GLD * 4;
        for (int idx = tid; idx < 128 * 8; idx += NTH) {
            const int r = idx >> 3;
            const int cB = (idx & 7) << 4;
            cpa16(Ab + r * GLD * 4 + cB, Arow + (size_t)r * Dc + kt * 32 + (cB >> 2));
        }
        for (int idx = tid; idx < BN * 8; idx += NTH) {
            const int r = idx >> 3;
            const int cB = (idx & 7) << 4;
            cpa16(Bb + r * GLD * 4 + cB, Brow + (size_t)r * Dc + kt * 32 + (cB >> 2));
        }
        asm volatile("cp.async.commit_group;");
    };

    float c[2][8][4] = {};                       // [mt][nt][frag]

    load_tile(0, 0);

    for (int kt = 0; kt < 24; kt++) {
        const int buf = kt & 1;
        if (kt < 23) {
            load_tile(kt + 1, buf ^ 1);
            asm volatile("cp.async.wait_group 1;");
        } else {
            asm volatile("cp.async.wait_group 0;");
        }
        __syncthreads();

        const uint32_t AbU = AsU + buf * 128 * GLD * 4;
        const uint32_t BbU = BsU + buf * BN * GLD * 4;
#pragma unroll
        for (int kk = 0; kk < 4; kk++) {
            const int klo = kk * 8;
            uint32_t a[2][4], bf[4][4];
#pragma unroll
            for (int mt = 0; mt < 2; mt++)
                lm4(a[mt][0], a[mt][1], a[mt][2], a[mt][3],
                    AbU + ((warp_m0 + mt * 16) * GLD + klo) * 4 + laneA);
#pragma unroll
            for (int g = 0; g < 4; g++)
                lm4(bf[g][0], bf[g][1], bf[g][2], bf[g][3],
                    BbU + ((warp_n0 + g * 16) * GLD + klo) * 4 + laneB);
#pragma unroll
            for (int mt = 0; mt < 2; mt++)
#pragma unroll
                for (int nt = 0; nt < 8; nt++) {
                    const int g = nt >> 1, hf = nt & 1;
                    mma_tf32(c[mt][nt], a[mt][0], a[mt][1], a[mt][2], a[mt][3],
                             bf[g][hf], bf[g][2 + hf]);
                }
        }
        __syncthreads();
    }

    if (MODE == 0) {
#pragma unroll
        for (int mt = 0; mt < 2; mt++)
#pragma unroll
            for (int nt = 0; nt < 8; nt++) {
                const int row = m0 + warp_m0 + mt * 16 + gr;
                const int col = n0g + warp_n0 + nt * 8 + 2 * gc;
                Cout[(size_t)(row    ) * Dc + col    ] = c[mt][nt][0];
                Cout[(size_t)(row    ) * Dc + col + 1] = c[mt][nt][1];
                Cout[(size_t)(row + 8) * Dc + col    ] = c[mt][nt][2];
                Cout[(size_t)(row + 8) * Dc + col + 1] = c[mt][nt][3];
            }
    } else {
        const int which = n0g / Dc;              // 256-tiles never straddle
        const int n0 = n0g % Dc;
        if (which < 2) {
            // ---- fused SiLU + RoPE for q/k ----
            float* dst = which ? g_k : g_q;
            float* cosS = (float*)sm;            // [128][68]
            float* sinS = cosS + 128 * 68;
            for (int idx = tid; idx < 128 * 16; idx += NTH) {
                const int r = idx >> 4;
                const int c4 = (idx & 15) << 2;
                *(float4*)&cosS[r * 68 + c4] =
                    *(const float4*)&cosp[(size_t)(m0 + r) * HDc + c4];
                *(float4*)&sinS[r * 68 + c4] =
                    *(const float4*)&sinp[(size_t)(m0 + r) * HDc + c4];
            }
            __syncthreads();
            const int h = (n0 + warp_n0) >> 6;
#pragma unroll
            for (int mt = 0; mt < 2; mt++)
#pragma unroll
                for (int half = 0; half < 2; half++)
#pragma unroll
                    for (int nt = 0; nt < 4; nt++)
#pragma unroll
                        for (int e = 0; e < 2; e++) {
                            const int r = warp_m0 + mt * 16 + half * 8 + gr;
                            const int d = nt * 8 + 2 * gc + e;
                            const float x1 = silu_fast(c[mt][nt    ][half * 2 + e]);
                            const float x2 = silu_fast(c[mt][nt + 4][half * 2 + e]);
                            const float c1 = cosS[r * 68 + d];
                            const float s1 = sinS[r * 68 + d];
                            const float c2 = cosS[r * 68 + d + 32];
                            const float s2 = sinS[r * 68 + d + 32];
                            const int m = m0 + r, b = m >> 11, l = m & 2047;
                            const size_t base = (((size_t)b * Hc + h) * Lc + l) * HDc;
                            dst[base + d] =
                                __uint_as_float(f2tf(x1 * c1 - x2 * s1));
                            dst[base + d + 32] =
                                __uint_as_float(f2tf(x2 * c2 + x1 * s2));
                        }
        } else {
            // ---- v: SiLU only ----
#pragma unroll
            for (int mt = 0; mt < 2; mt++)
#pragma unroll
                for (int nt = 0; nt < 8; nt++)
#pragma unroll
                    for (int half = 0; half < 2; half++)
#pragma unroll
                        for (int e = 0; e < 2; e++) {
                            const int row = m0 + warp_m0 + mt * 16 + half * 8 + gr;
                            const int colL = n0 + warp_n0 + nt * 8 + 2 * gc + e;
                            const int hh = colL >> 6, d = colL & 63;
                            const int b = row >> 11, l = row & 2047;
                            g_v[(((size_t)b * Hc + hh) * Lc + l) * HDc + d] =
                                __uint_as_float(f2tf(silu_fast(c[mt][nt][half * 2 + e])));
                        }
        }
    }
}

// ---------------------------------------------------------------------------
// Kernel 2: causal attention, mma.sync tf32. cp.async double-buffered K/V
// staging (V transposed smem->smem). SiLU via approx ops. 128-row q tiles,
// 512 threads, 16 warps (8m x 2n), qt-descending schedule.
// ---------------------------------------------------------------------------
constexpr int ALD = 68;                              // smem row pitch (floats)
constexpr int ATTN_SMEM = (5 * 64 + 128) * ALD * 4;  // Kb2,Vb2,Vt,Ss = 121856 B
constexpr int QTILES = Lc / 128;                     // 16

__global__ __launch_bounds__(512, 1)
void attn_mma_kernel(float* __restrict__ attn_out) {
    extern __shared__ uint32_t sm[];
    uint32_t* Kb = sm;                        // [2][64][ALD] K rows
    uint32_t* Vb = sm + 2 * 64 * ALD;         // [2][64][ALD] V rows (raw)
    uint32_t* Vt = sm + 4 * 64 * ALD;         // [64][ALD]   V transposed
    float*    Ss = (float*)(sm + 5 * 64 * ALD);   // [128][ALD]

    const int tid = threadIdx.x;
    const int warp = tid >> 5, lane = tid & 31;
    const int gr = lane >> 2, gc = lane & 3;
    const int qt = QTILES - 1 - (int)blockIdx.x / BH;
    const int bh = (int)blockIdx.x % BH;
    const int q0 = qt * 128;

    const int warp_m0 = (warp >> 1) * 16;   // 8 warps in m
    const int warp_n0 = (warp & 1) * 32;    // 2 warps in n

    const uint32_t laneA = ((lane & 15) * ALD + 4 * (lane >> 4)) * 4;
    const uint32_t laneB4 = ((((lane >> 3) & 1) * 8 + (lane & 7)) * ALD) * 4
                          + (lane >> 4) * 16;
    const uint32_t KbU = s2u(Kb), VtU = s2u(Vt), SsU = s2u(Ss);

    const float* Qg = g_q + (size_t)bh * Lc * HDc;
    const float* Kg = g_k + (size_t)bh * Lc * HDc;
    const float* Vg = g_v + (size_t)bh * Lc * HDc;
    float* attn_base = attn_out + (size_t)bh * Lc * Lc;

    auto load_kv = [&](int kt, int buf) {
        const uint32_t kB = KbU + buf * 64 * ALD * 4;
        const uint32_t vB = kB + 2 * 64 * ALD * 4;   // Vb mirrors Kb layout
#pragma unroll
        for (int i = 0; i < 2; i++) {
            const int idx = tid + i * 512;           // 1024 chunks of 16B
            const int r = idx >> 4;
            const int cB = (idx & 15) << 4;
            cpa16(kB + r * ALD * 4 + cB, Kg + (size_t)(kt * 64 + r) * HDc + (cB >> 2));
            cpa16(vB + r * ALD * 4 + cB, Vg + (size_t)(kt * 64 + r) * HDc + (cB >> 2));
        }
        asm volatile("cp.async.commit_group;");
    };

    load_kv(0, 0);

    // Stage Q (pre-rounded) into Ss, preload Q fragments.
#pragma unroll
    for (int i = 0; i < 4; i++) {
        const int idx = tid + i * 512;
        const int r = idx >> 4;
        const int c4 = (idx & 15) << 2;
        *(float4*)&Ss[r * ALD + c4] = *(const float4*)&Qg[(size_t)(q0 + r) * HDc + c4];
    }
    __syncthreads();

    uint32_t qf[8][4];
#pragma unroll
    for (int kk = 0; kk < 8; kk++)
        lm4(qf[kk][0], qf[kk][1], qf[kk][2], qf[kk][3],
            SsU + (warp_m0 * ALD + kk * 8) * 4 + laneA);

    float o[4][4] = {};
    const int ktn = 2 * qt + 2;

    for (int kt = 0; kt < ktn; kt++) {
        const int cur = kt & 1;
        if (kt + 1 < ktn) {
            load_kv(kt + 1, cur ^ 1);
            asm volatile("cp.async.wait_group 1;");
        } else {
            asm volatile("cp.async.wait_group 0;");
        }
        __syncthreads();      // buffers[cur] ready; prev iter's Ss/Vt reads done

        // Transpose Vb[cur] -> Vt
        {
            const uint32_t* Vbp = Vb + cur * 64 * ALD;
            const int d = tid & 63;
            const int rg = tid >> 6;          // 0..7, k-base rg*8
            uint32_t t0[4], t1[4];
#pragma unroll
            for (int j = 0; j < 4; j++) t0[j] = Vbp[(rg * 8 + j) * ALD + d];
#pragma unroll
            for (int j = 0; j < 4; j++) t1[j] = Vbp[(rg * 8 + 4 + j) * ALD + d];
            *(uint4*)&Vt[d * ALD + rg * 8]     = *(uint4*)t0;
            *(uint4*)&Vt[d * ALD + rg * 8 + 4] = *(uint4*)t1;
        }

        // S = Q K^T from Kb[cur]
        const uint32_t kBU = KbU + cur * 64 * ALD * 4;
        float s[4][4] = {};
#pragma unroll
        for (int kk = 0; kk < 8; kk++) {
            uint32_t bf[2][4];
#pragma unroll
            for (int g = 0; g < 2; g++)
                lm4(bf[g][0], bf[g][1], bf[g][2], bf[g][3],
                    kBU + ((warp_n0 + g * 16) * ALD + kk * 8) * 4 + laneB4);
#pragma unroll
            for (int nt = 0; nt < 4; nt++) {
                const int g = nt >> 1, hf = nt & 1;
                mma_tf32(s[nt], qf[kk][0], qf[kk][1], qf[kk][2], qf[kk][3],
                         bf[g][hf], bf[g][2 + hf]);
            }
        }

        // mask + silu/L -> Ss (approx silu: 1 EX2 + 1 RCP)
#pragma unroll
        for (int nt = 0; nt < 4; nt++)
#pragma unroll
            for (int half = 0; half < 2; half++)
#pragma unroll
                for (int e = 0; e < 2; e++) {
                    const int row = warp_m0 + half * 8 + gr;
                    const int col = warp_n0 + nt * 8 + 2 * gc + e;
                    const int q = q0 + row;
                    const int k = kt * 64 + col;
                    const float x = s[nt][half * 2 + e];
                    Ss[row * ALD + col] =
                        (k <= q) ? silu_fast(x) * (1.0f / Lc) : 0.0f;
                }
        __syncthreads();      // Vt + Ss ready

        // attn gmem write (float4)
#pragma unroll
        for (int i = 0; i < 4; i++) {
            const int idx = tid + i * 512;
            const int r = idx >> 4;
            const int c4 = (idx & 15) << 2;
            *(float4*)&attn_base[(size_t)(q0 + r) * Lc + kt * 64 + c4] =
                *(const float4*)&Ss[r * ALD + c4];
        }

        // O += S @ V
#pragma unroll
        for (int kk = 0; kk < 8; kk++) {
            const int klo = kk * 8;
            uint32_t a[4], bf[2][4];
            lm4(a[0], a[1], a[2], a[3],
                SsU + (warp_m0 * ALD + klo) * 4 + laneA);
#pragma unroll
            for (int j = 0; j < 4; j++)
                a[j] = f2tf(__uint_as_float(a[j]));
#pragma unroll
            for (int g = 0; g < 2; g++)
                lm4(bf[g][0], bf[g][1], bf[g][2], bf[g][3],
                    VtU + ((warp_n0 + g * 16) * ALD + klo) * 4 + laneB4);
#pragma unroll
            for (int nt = 0; nt < 4; nt++) {
                const int g = nt >> 1, hf = nt & 1;
                mma_tf32(o[nt], a[0], a[1], a[2], a[3], bf[g][hf], bf[g][2 + hf]);
            }
        }
    }

    // Zero-fill strictly-upper region (k >= q0+128)
    const int zstart = q0 + 128;
    const int zcols = Lc - zstart;
    if (zcols > 0) {
        const int row4 = zcols >> 2;
        const int tot4 = 128 * row4;
        for (int e = tid; e < tot4; e += 512) {
            const int row = e / row4;
            const int c4 = (e % row4) << 2;
            *(float4*)&attn_base[(size_t)(q0 + row) * Lc + zstart + c4] =
                make_float4(0.f, 0.f, 0.f, 0.f);
        }
    }

    // Write O (tf32-rounded, feeds cp.async output projection)
    const int b = bh / Hc;
    const int h = bh % Hc;
#pragma unroll
    for (int nt = 0; nt < 4; nt++)
#pragma unroll
        for (int half = 0; half < 2; half++)
#pragma unroll
            for (int e = 0; e < 2; e++) {
                const int row = q0 + warp_m0 + half * 8 + gr;
                const int d = warp_n0 + nt * 8 + 2 * gc + e;
                g_o[((size_t)b * Lc + row) * Dc + h * HDc + d] =
                    __uint_as_float(f2tf(o[nt][half * 2 + e]));
            }
}

// ---------------------------------------------------------------------------
// Launch. Inputs: hidden_states, attention_mask, cos, sin, Wq, Wk, Wv, Wo.
// Output: [attn_output (B*L*D) | attn (B*H*L*L)]. Mask handled analytically.
// ---------------------------------------------------------------------------
extern "C" void kernel_launch(void* const* d_in, const int* in_sizes, int n_in,
                              void* d_out, int out_size) {
    const float* hidden = (const float*)d_in[0];
    const float* cosp   = (const float*)d_in[2];
    const float* sinp   = (const float*)d_in[3];
    const float* Wq     = (const float*)d_in[4];
    const float* Wk     = (const float*)d_in[5];
    const float* Wv     = (const float*)d_in[6];
    const float* Wo     = (const float*)d_in[7];

    float* out = (float*)d_out;
    float* attn_out = out + (size_t)Bc * Lc * Dc;

    cudaFuncSetAttribute((const void*)gemm_tf32_kernel<1, 256>,
                         cudaFuncAttributeMaxDynamicSharedMemorySize, gemm_smem(256));
    cudaFuncSetAttribute((const void*)gemm_tf32_kernel<0, 192>,
                         cudaFuncAttributeMaxDynamicSharedMemorySize, gemm_smem(192));
    cudaFuncSetAttribute(attn_mma_kernel,
                         cudaFuncAttributeMaxDynamicSharedMemorySize, ATTN_SMEM);

    // 0) One fused tf32-rounding pass (hidden + all weights).
    cvt_all_kernel<<<(CVT_TOT + 255) / 256, 256>>>(
        (const float4*)hidden, (const float4*)Wq, (const float4*)Wk,
        (const float4*)Wv, (const float4*)Wo);

    // 1) QKV projections + SiLU + fused RoPE (128x256 tiles)
    gemm_tf32_kernel<1, 256><<<dim3(3 * Dc / 256, Mrows / 128), 512, gemm_smem(256)>>>(
        nullptr, cosp, sinp);

    // 2) Attention (qt-descending 1D schedule, cp.async pipelined)
    attn_mma_kernel<<<QTILES * BH, 512, ATTN_SMEM>>>(attn_out);

    // 3) Output projection (128x192 tiles -> 128-CTA single wave)
    gemm_tf32_kernel<0, 192><<<dim3(Dc / 192, Mrows / 128), 384, gemm_smem(192)>>>(
        out, nullptr, nullptr);
}

// round 13
// speedup vs baseline: 1.5147x; 1.5147x over previous
#include <cuda_runtime.h>
#include <cuda_bf16.h>
#include <cstdint>

// Problem constants
constexpr int Bc  = 2;
constexpr int Lc  = 2048;
constexpr int Dc  = 768;
constexpr int Hc  = 12;
constexpr int HDc = 64;
constexpr int BH  = Bc * Hc;            // 24
constexpr int Mrows = Bc * Lc;          // 4096

// Scratch (device globals; no allocation allowed)
__device__ __align__(128) float g_q[(size_t)BH * Lc * HDc];   // [b,h,l,d] tf32 (post-RoPE)
__device__ __align__(128) float g_k[(size_t)BH * Lc * HDc];
__device__ __align__(128) float g_v[(size_t)BH * Lc * HDc];
__device__ __align__(128) float g_o[(size_t)Bc * Lc * Dc];    // [b,l,h*64+d] tf32
__device__ __align__(128) float g_hid_tf[(size_t)Mrows * Dc];
__device__ __align__(128) float g_w_tf[(size_t)3 * Dc * Dc];
__device__ __align__(128) float g_wo_tf[(size_t)Dc * Dc];

__device__ __forceinline__ float silu_f(float x) {
    return x / (1.0f + __expf(-x));
}

// Fast SiLU for the attention hot loop: 2 MUFU + 2 FMA, flag-independent.
__device__ __forceinline__ float silu_fast(float x) {
    float e, r;
    asm("ex2.approx.f32 %0, %1;" : "=f"(e) : "f"(-x * 1.4426950408889634f));
    asm("rcp.approx.f32 %0, %1;" : "=f"(r) : "f"(1.0f + e));
    return x * r;
}

__device__ __forceinline__ uint32_t f2tf(float x) {
    uint32_t r;
    asm("cvt.rna.tf32.f32 %0, %1;" : "=r"(r) : "f"(x));
    return r;
}

__device__ __forceinline__ uint32_t s2u(const void* p) {
    return (uint32_t)__cvta_generic_to_shared(p);
}

__device__ __forceinline__ void lm4(uint32_t& r0, uint32_t& r1,
                                    uint32_t& r2, uint32_t& r3, uint32_t addr) {
    asm volatile("ldmatrix.sync.aligned.m8n8.x4.shared.b16 {%0,%1,%2,%3},[%4];"
                 : "=r"(r0), "=r"(r1), "=r"(r2), "=r"(r3) : "r"(addr));
}

__device__ __forceinline__ void mma_tf32(float c[4],
                                         uint32_t a0, uint32_t a1, uint32_t a2, uint32_t a3,
                                         uint32_t b0, uint32_t b1) {
    asm volatile(
        "mma.sync.aligned.m16n8k8.row.col.f32.tf32.tf32.f32 "
        "{%0,%1,%2,%3},{%4,%5,%6,%7},{%8,%9},{%0,%1,%2,%3};"
        : "+f"(c[0]), "+f"(c[1]), "+f"(c[2]), "+f"(c[3])
        : "r"(a0), "r"(a1), "r"(a2), "r"(a3), "r"(b0), "r"(b1));
}

__device__ __forceinline__ void cpa16(uint32_t s, const void* g) {
    asm volatile("cp.async.cg.shared.global [%0], [%1], 16;" :: "r"(s), "l"(g));
}

// ---------------------------------------------------------------------------
// Kernel 0: single fused tf32-rounding pass over hidden + 4 weights.
// ---------------------------------------------------------------------------
constexpr int HID4 = Mrows * Dc / 4;    // 786432
constexpr int W4   = Dc * Dc / 4;       // 147456
constexpr int CVT_TOT = HID4 + 4 * W4;  // 1376256

__global__ void cvt_all_kernel(const float4* __restrict__ hid,
                               const float4* __restrict__ wq,
                               const float4* __restrict__ wk,
                               const float4* __restrict__ wv,
                               const float4* __restrict__ wo) {
    const int i = blockIdx.x * blockDim.x + threadIdx.x;
    if (i >= CVT_TOT) return;
    const float4* src;
    float4* dst;
    int off;
    if (i < HID4) {
        src = hid; dst = (float4*)g_hid_tf; off = i;
    } else {
        const int j = i - HID4;
        const int w = j / W4;
        off = j - w * W4;
        src = (w == 0) ? wq : (w == 1) ? wk : (w == 2) ? wv : wo;
        dst = (w < 3) ? (float4*)g_w_tf + (size_t)w * W4 : (float4*)g_wo_tf;
    }
    float4 v = src[off];
    float4 r;
    r.x = __uint_as_float(f2tf(v.x));
    r.y = __uint_as_float(f2tf(v.y));
    r.z = __uint_as_float(f2tf(v.z));
    r.w = __uint_as_float(f2tf(v.w));
    dst[off] = r;
}

// ---------------------------------------------------------------------------
// Kernel 1: tf32 GEMM, C[M,N] = A[M,768] * B[N,768]^T, inputs pre-rounded.
// CTA tile 128x256, BK=32, 512 threads / 16 warps (4m x 4n), warp tile 32x64.
// cp.async double-buffered staging, all fragments via ldmatrix.x4.
// MODE 1: A=g_hid_tf, B=g_w_tf (Wq|Wk|Wv). Epilogue: SiLU, then for q/k the
//         FUSED RoPE, round, scatter to g_q/g_k/g_v.
// MODE 0: A=g_o, B=g_wo_tf, plain write to Cout.
// ---------------------------------------------------------------------------
constexpr int GLD = 36;                        // smem row pitch (floats), 144B
constexpr int GEMM_SMEM = 2 * (128 + 256) * GLD * 4;   // 110592 B

template<int MODE>
__global__ __launch_bounds__(512, 1)
void gemm_tf32_kernel(float* __restrict__ Cout,
                      const float* __restrict__ cosp,
                      const float* __restrict__ sinp) {
    extern __shared__ uint32_t sm[];
    uint32_t* As = sm;                          // [2][128*GLD]
    uint32_t* Bs = sm + 2 * 128 * GLD;          // [2][256*GLD]

    const int tid = threadIdx.x;
    const int warp = tid >> 5, lane = tid & 31;
    const int gr = lane >> 2, gc = lane & 3;
    const int m0 = blockIdx.y * 128;
    const int n0g = blockIdx.x * 256;

    const float* Arow = ((MODE == 1) ? g_hid_tf : g_o) + (size_t)m0 * Dc;
    const float* Brow = ((MODE == 1) ? g_w_tf : g_wo_tf) + (size_t)n0g * Dc;

    const int warp_m0 = (warp >> 2) * 32;       // 4 warps in m
    const int warp_n0 = (warp & 3) * 64;        // 4 warps in n

    const uint32_t laneA = ((lane & 15) * GLD + 4 * (lane >> 4)) * 4;
    const uint32_t laneB = ((((lane >> 3) & 1) * 8 + (lane & 7)) * GLD) * 4
                         + (lane >> 4) * 16;
    const uint32_t AsU = s2u(As), BsU = s2u(Bs);

    auto load_tile = [&](int kt, int buf) {
        uint32_t Ab = AsU + buf * 128 * GLD * 4;
        uint32_t Bb = BsU + buf * 256 * GLD * 4;
#pragma unroll
        for (int i = 0; i < 2; i++) {            // A: 128 rows x 8 chunks
            const int idx = tid + i * 512;
            const int r = idx >> 3;
            const int cB = (idx & 7) << 4;
            cpa16(Ab + r * GLD * 4 + cB, Arow + (size_t)r * Dc + kt * 32 + (cB >> 2));
        }
#pragma unroll
        for (int i = 0; i < 4; i++) {            // B: 256 rows x 8 chunks
            const int idx = tid + i * 512;
            const int r = idx >> 3;
            const int cB = (idx & 7) << 4;
            cpa16(Bb + r * GLD * 4 + cB, Brow + (size_t)r * Dc + kt * 32 + (cB >> 2));
        }
        asm volatile("cp.async.commit_group;");
    };

    float c[2][8][4] = {};                       // [mt][nt][frag]

    load_tile(0, 0);

    for (int kt = 0; kt < 24; kt++) {
        const int buf = kt & 1;
        if (kt < 23) {
            load_tile(kt + 1, buf ^ 1);
            asm volatile("cp.async.wait_group 1;");
        } else {
            asm volatile("cp.async.wait_group 0;");
        }
        __syncthreads();

        const uint32_t AbU = AsU + buf * 128 * GLD * 4;
        const uint32_t BbU = BsU + buf * 256 * GLD * 4;
#pragma unroll
        for (int kk = 0; kk < 4; kk++) {
            const int klo = kk * 8;
            uint32_t a[2][4], bf[4][4];
#pragma unroll
            for (int mt = 0; mt < 2; mt++)
                lm4(a[mt][0], a[mt][1], a[mt][2], a[mt][3],
                    AbU + ((warp_m0 + mt * 16) * GLD + klo) * 4 + laneA);
#pragma unroll
            for (int g = 0; g < 4; g++)
                lm4(bf[g][0], bf[g][1], bf[g][2], bf[g][3],
                    BbU + ((warp_n0 + g * 16) * GLD + klo) * 4 + laneB);
#pragma unroll
            for (int mt = 0; mt < 2; mt++)
#pragma unroll
                for (int nt = 0; nt < 8; nt++) {
                    const int g = nt >> 1, hf = nt & 1;
                    mma_tf32(c[mt][nt], a[mt][0], a[mt][1], a[mt][2], a[mt][3],
                             bf[g][hf], bf[g][2 + hf]);
                }
        }
        __syncthreads();
    }

    if (MODE == 0) {
#pragma unroll
        for (int mt = 0; mt < 2; mt++)
#pragma unroll
            for (int nt = 0; nt < 8; nt++) {
                const int row = m0 + warp_m0 + mt * 16 + gr;
                const int col = n0g + warp_n0 + nt * 8 + 2 * gc;
                Cout[(size_t)(row    ) * Dc + col    ] = c[mt][nt][0];
                Cout[(size_t)(row    ) * Dc + col + 1] = c[mt][nt][1];
                Cout[(size_t)(row + 8) * Dc + col    ] = c[mt][nt][2];
                Cout[(size_t)(row + 8) * Dc + col + 1] = c[mt][nt][3];
            }
    } else {
        const int which = n0g / Dc;              // 256-tiles never straddle
        const int n0 = n0g % Dc;
        if (which < 2) {
            // ---- fused SiLU + RoPE for q/k ----
            float* dst = which ? g_k : g_q;
            float* cosS = (float*)sm;            // [128][68]
            float* sinS = cosS + 128 * 68;
#pragma unroll
            for (int i = 0; i < 4; i++) {
                const int idx = tid + i * 512;   // 2048 float4
                const int r = idx >> 4;
                const int c4 = (idx & 15) << 2;
                *(float4*)&cosS[r * 68 + c4] =
                    *(const float4*)&cosp[(size_t)(m0 + r) * HDc + c4];
                *(float4*)&sinS[r * 68 + c4] =
                    *(const float4*)&sinp[(size_t)(m0 + r) * HDc + c4];
            }
            __syncthreads();
            const int h = (n0 + warp_n0) >> 6;
#pragma unroll
            for (int mt = 0; mt < 2; mt++)
#pragma unroll
                for (int half = 0; half < 2; half++)
#pragma unroll
                    for (int nt = 0; nt < 4; nt++)
#pragma unroll
                        for (int e = 0; e < 2; e++) {
                            const int r = warp_m0 + mt * 16 + half * 8 + gr;
                            const int d = nt * 8 + 2 * gc + e;
                            const float x1 = silu_f(c[mt][nt    ][half * 2 + e]);
                            const float x2 = silu_f(c[mt][nt + 4][half * 2 + e]);
                            const float c1 = cosS[r * 68 + d];
                            const float s1 = sinS[r * 68 + d];
                            const float c2 = cosS[r * 68 + d + 32];
                            const float s2 = sinS[r * 68 + d + 32];
                            const int m = m0 + r, b = m >> 11, l = m & 2047;
                            const size_t base = (((size_t)b * Hc + h) * Lc + l) * HDc;
                            dst[base + d] =
                                __uint_as_float(f2tf(x1 * c1 - x2 * s1));
                            dst[base + d + 32] =
                                __uint_as_float(f2tf(x2 * c2 + x1 * s2));
                        }
        } else {
            // ---- v: SiLU only ----
#pragma unroll
            for (int mt = 0; mt < 2; mt++)
#pragma unroll
                for (int nt = 0; nt < 8; nt++)
#pragma unroll
                    for (int half = 0; half < 2; half++)
#pragma unroll
                        for (int e = 0; e < 2; e++) {
                            const int row = m0 + warp_m0 + mt * 16 + half * 8 + gr;
                            const int colL = n0 + warp_n0 + nt * 8 + 2 * gc + e;
                            const int hh = colL >> 6, d = colL & 63;
                            const int b = row >> 11, l = row & 2047;
                            g_v[(((size_t)b * Hc + hh) * Lc + l) * HDc + d] =
                                __uint_as_float(f2tf(silu_f(c[mt][nt][half * 2 + e])));
                        }
        }
    }
}

// ---------------------------------------------------------------------------
// Kernel 2: causal attention, mma.sync tf32. cp.async double-buffered K/V
// staging (V transposed smem->smem). 128-row q tiles, 512 threads, 16 warps
// (8m x 2n), qt-descending schedule. SiLU via approx ops (ONLY change vs R10).
// ---------------------------------------------------------------------------
constexpr int ALD = 68;                              // smem row pitch (floats)
constexpr int ATTN_SMEM = (5 * 64 + 128) * ALD * 4;  // Kb2,Vb2,Vt,Ss = 121856 B
constexpr int QTILES = Lc / 128;                     // 16

__global__ __launch_bounds__(512, 1)
void attn_mma_kernel(float* __restrict__ attn_out) {
    extern __shared__ uint32_t sm[];
    uint32_t* Kb = sm;                        // [2][64][ALD] K rows
    uint32_t* Vb = sm + 2 * 64 * ALD;         // [2][64][ALD] V rows (raw)
    uint32_t* Vt = sm + 4 * 64 * ALD;         // [64][ALD]   V transposed
    float*    Ss = (float*)(sm + 5 * 64 * ALD);   // [128][ALD]

    const int tid = threadIdx.x;
    const int warp = tid >> 5, lane = tid & 31;
    const int gr = lane >> 2, gc = lane & 3;
    const int qt = QTILES - 1 - (int)blockIdx.x / BH;
    const int bh = (int)blockIdx.x % BH;
    const int q0 = qt * 128;

    const int warp_m0 = (warp >> 1) * 16;   // 8 warps in m
    const int warp_n0 = (warp & 1) * 32;    // 2 warps in n

    const uint32_t laneA = ((lane & 15) * ALD + 4 * (lane >> 4)) * 4;
    const uint32_t laneB4 = ((((lane >> 3) & 1) * 8 + (lane & 7)) * ALD) * 4
                          + (lane >> 4) * 16;
    const uint32_t KbU = s2u(Kb), VtU = s2u(Vt), SsU = s2u(Ss);

    const float* Qg = g_q + (size_t)bh * Lc * HDc;
    const float* Kg = g_k + (size_t)bh * Lc * HDc;
    const float* Vg = g_v + (size_t)bh * Lc * HDc;
    float* attn_base = attn_out + (size_t)bh * Lc * Lc;

    auto load_kv = [&](int kt, int buf) {
        const uint32_t kB = KbU + buf * 64 * ALD * 4;
        const uint32_t vB = kB + 2 * 64 * ALD * 4;   // Vb mirrors Kb layout
#pragma unroll
        for (int i = 0; i < 2; i++) {
            const int idx = tid + i * 512;           // 1024 chunks of 16B
            const int r = idx >> 4;
            const int cB = (idx & 15) << 4;
            cpa16(kB + r * ALD * 4 + cB, Kg + (size_t)(kt * 64 + r) * HDc + (cB >> 2));
            cpa16(vB + r * ALD * 4 + cB, Vg + (size_t)(kt * 64 + r) * HDc + (cB >> 2));
        }
        asm volatile("cp.async.commit_group;");
    };

    load_kv(0, 0);

    // Stage Q (pre-rounded) into Ss, preload Q fragments.
#pragma unroll
    for (int i = 0; i < 4; i++) {
        const int idx = tid + i * 512;
        const int r = idx >> 4;
        const int c4 = (idx & 15) << 2;
        *(float4*)&Ss[r * ALD + c4] = *(const float4*)&Qg[(size_t)(q0 + r) * HDc + c4];
    }
    __syncthreads();

    uint32_t qf[8][4];
#pragma unroll
    for (int kk = 0; kk < 8; kk++)
        lm4(qf[kk][0], qf[kk][1], qf[kk][2], qf[kk][3],
            SsU + (warp_m0 * ALD + kk * 8) * 4 + laneA);

    float o[4][4] = {};
    const int ktn = 2 * qt + 2;

    for (int kt = 0; kt < ktn; kt++) {
        const int cur = kt & 1;
        if (kt + 1 < ktn) {
            load_kv(kt + 1, cur ^ 1);
            asm volatile("cp.async.wait_group 1;");
        } else {
            asm volatile("cp.async.wait_group 0;");
        }
        __syncthreads();      // buffers[cur] ready; prev iter's Ss/Vt reads done

        // Transpose Vb[cur] -> Vt
        {
            const uint32_t* Vbp = Vb + cur * 64 * ALD;
            const int d = tid & 63;
            const int rg = tid >> 6;          // 0..7, k-base rg*8
            uint32_t t0[4], t1[4];
#pragma unroll
            for (int j = 0; j < 4; j++) t0[j] = Vbp[(rg * 8 + j) * ALD + d];
#pragma unroll
            for (int j = 0; j < 4; j++) t1[j] = Vbp[(rg * 8 + 4 + j) * ALD + d];
            *(uint4*)&Vt[d * ALD + rg * 8]     = *(uint4*)t0;
            *(uint4*)&Vt[d * ALD + rg * 8 + 4] = *(uint4*)t1;
        }

        // S = Q K^T from Kb[cur]
        const uint32_t kBU = KbU + cur * 64 * ALD * 4;
        float s[4][4] = {};
#pragma unroll
        for (int kk = 0; kk < 8; kk++) {
            uint32_t bf[2][4];
#pragma unroll
            for (int g = 0; g < 2; g++)
                lm4(bf[g][0], bf[g][1], bf[g][2], bf[g][3],
                    kBU + ((warp_n0 + g * 16) * ALD + kk * 8) * 4 + laneB4);
#pragma unroll
            for (int nt = 0; nt < 4; nt++) {
                const int g = nt >> 1, hf = nt & 1;
                mma_tf32(s[nt], qf[kk][0], qf[kk][1], qf[kk][2], qf[kk][3],
                         bf[g][hf], bf[g][2 + hf]);
            }
        }

        // mask + silu/L -> Ss (approx silu: 1 EX2 + 1 RCP)
#pragma unroll
        for (int nt = 0; nt < 4; nt++)
#pragma unroll
            for (int half = 0; half < 2; half++)
#pragma unroll
                for (int e = 0; e < 2; e++) {
                    const int row = warp_m0 + half * 8 + gr;
                    const int col = warp_n0 + nt * 8 + 2 * gc + e;
                    const int q = q0 + row;
                    const int k = kt * 64 + col;
                    const float x = s[nt][half * 2 + e];
                    Ss[row * ALD + col] =
                        (k <= q) ? silu_fast(x) * (1.0f / Lc) : 0.0f;
                }
        __syncthreads();      // Vt + Ss ready

        // attn gmem write (float4)
#pragma unroll
        for (int i = 0; i < 4; i++) {
            const int idx = tid + i * 512;
            const int r = idx >> 4;
            const int c4 = (idx & 15) << 2;
            *(float4*)&attn_base[(size_t)(q0 + r) * Lc + kt * 64 + c4] =
                *(const float4*)&Ss[r * ALD + c4];
        }

        // O += S @ V
#pragma unroll
        for (int kk = 0; kk < 8; kk++) {
            const int klo = kk * 8;
            uint32_t a[4], bf[2][4];
            lm4(a[0], a[1], a[2], a[3],
                SsU + (warp_m0 * ALD + klo) * 4 + laneA);
#pragma unroll
            for (int j = 0; j < 4; j++)
                a[j] = f2tf(__uint_as_float(a[j]));
#pragma unroll
            for (int g = 0; g < 2; g++)
                lm4(bf[g][0], bf[g][1], bf[g][2], bf[g][3],
                    VtU + ((warp_n0 + g * 16) * ALD + klo) * 4 + laneB4);
#pragma unroll
            for (int nt = 0; nt < 4; nt++) {
                const int g = nt >> 1, hf = nt & 1;
                mma_tf32(o[nt], a[0], a[1], a[2], a[3], bf[g][hf], bf[g][2 + hf]);
            }
        }
    }

    // Zero-fill strictly-upper region (k >= q0+128)
    const int zstart = q0 + 128;
    const int zcols = Lc - zstart;
    if (zcols > 0) {
        const int row4 = zcols >> 2;
        const int tot4 = 128 * row4;
        for (int e = tid; e < tot4; e += 512) {
            const int row = e / row4;
            const int c4 = (e % row4) << 2;
            *(float4*)&attn_base[(size_t)(q0 + row) * Lc + zstart + c4] =
                make_float4(0.f, 0.f, 0.f, 0.f);
        }
    }

    // Write O (tf32-rounded, feeds cp.async output projection)
    const int b = bh / Hc;
    const int h = bh % Hc;
#pragma unroll
    for (int nt = 0; nt < 4; nt++)
#pragma unroll
        for (int half = 0; half < 2; half++)
#pragma unroll
            for (int e = 0; e < 2; e++) {
                const int row = q0 + warp_m0 + half * 8 + gr;
                const int d = warp_n0 + nt * 8 + 2 * gc + e;
                g_o[((size_t)b * Lc + row) * Dc + h * HDc + d] =
                    __uint_as_float(f2tf(o[nt][half * 2 + e]));
            }
}

// ---------------------------------------------------------------------------
// Launch. Inputs: hidden_states, attention_mask, cos, sin, Wq, Wk, Wv, Wo.
// Output: [attn_output (B*L*D) | attn (B*H*L*L)]. Mask handled analytically.
// ---------------------------------------------------------------------------
extern "C" void kernel_launch(void* const* d_in, const int* in_sizes, int n_in,
                              void* d_out, int out_size) {
    const float* hidden = (const float*)d_in[0];
    const float* cosp   = (const float*)d_in[2];
    const float* sinp   = (const float*)d_in[3];
    const float* Wq     = (const float*)d_in[4];
    const float* Wk     = (const float*)d_in[5];
    const float* Wv     = (const float*)d_in[6];
    const float* Wo     = (const float*)d_in[7];

    float* out = (float*)d_out;
    float* attn_out = out + (size_t)Bc * Lc * Dc;

    cudaFuncSetAttribute(gemm_tf32_kernel<1>,
                         cudaFuncAttributeMaxDynamicSharedMemorySize, GEMM_SMEM);
    cudaFuncSetAttribute(gemm_tf32_kernel<0>,
                         cudaFuncAttributeMaxDynamicSharedMemorySize, GEMM_SMEM);
    cudaFuncSetAttribute(attn_mma_kernel,
                         cudaFuncAttributeMaxDynamicSharedMemorySize, ATTN_SMEM);

    // 0) One fused tf32-rounding pass (hidden + all weights).
    cvt_all_kernel<<<(CVT_TOT + 255) / 256, 256>>>(
        (const float4*)hidden, (const float4*)Wq, (const float4*)Wk,
        (const float4*)Wv, (const float4*)Wo);

    // 1) QKV projections + SiLU + fused RoPE (128x256 tiles)
    gemm_tf32_kernel<1><<<dim3(3 * Dc / 256, Mrows / 128), 512, GEMM_SMEM>>>(
        nullptr, cosp, sinp);

    // 2) Attention (qt-descending 1D schedule, cp.async pipelined)
    attn_mma_kernel<<<QTILES * BH, 512, ATTN_SMEM>>>(attn_out);

    // 3) Output projection (128x256 tiles, 96-CTA wave — as R10)
    gemm_tf32_kernel<0><<<dim3(Dc / 256, Mrows / 128), 512, GEMM_SMEM>>>(
        out, nullptr, nullptr);
}

// round 14
// speedup vs baseline: 1.5536x; 1.0257x over previous
#include <cuda_runtime.h>
#include <cuda_bf16.h>
#include <cstdint>

// Problem constants
constexpr int Bc  = 2;
constexpr int Lc  = 2048;
constexpr int Dc  = 768;
constexpr int Hc  = 12;
constexpr int HDc = 64;
constexpr int BH  = Bc * Hc;            // 24
constexpr int Mrows = Bc * Lc;          // 4096

// Scratch (device globals; no allocation allowed)
__device__ __align__(128) float g_q[(size_t)BH * Lc * HDc];   // [b,h,l,d] tf32 (post-RoPE)
__device__ __align__(128) float g_k[(size_t)BH * Lc * HDc];
__device__ __align__(128) float g_v[(size_t)BH * Lc * HDc];
__device__ __align__(128) float g_o[(size_t)Bc * Lc * Dc];    // [b,l,h*64+d] tf32
__device__ __align__(128) float g_hid_tf[(size_t)Mrows * Dc];
__device__ __align__(128) float g_w_tf[(size_t)3 * Dc * Dc];
__device__ __align__(128) float g_wo_tf[(size_t)Dc * Dc];

__device__ __forceinline__ float silu_f(float x) {
    return x / (1.0f + __expf(-x));
}

// Fast SiLU: 2 MUFU + 2 FMA, flag-independent.
__device__ __forceinline__ float silu_fast(float x) {
    float e, r;
    asm("ex2.approx.f32 %0, %1;" : "=f"(e) : "f"(-x * 1.4426950408889634f));
    asm("rcp.approx.f32 %0, %1;" : "=f"(r) : "f"(1.0f + e));
    return x * r;
}

__device__ __forceinline__ uint32_t f2tf(float x) {
    uint32_t r;
    asm("cvt.rna.tf32.f32 %0, %1;" : "=r"(r) : "f"(x));
    return r;
}

__device__ __forceinline__ uint32_t s2u(const void* p) {
    return (uint32_t)__cvta_generic_to_shared(p);
}

__device__ __forceinline__ void lm4(uint32_t& r0, uint32_t& r1,
                                    uint32_t& r2, uint32_t& r3, uint32_t addr) {
    asm volatile("ldmatrix.sync.aligned.m8n8.x4.shared.b16 {%0,%1,%2,%3},[%4];"
                 : "=r"(r0), "=r"(r1), "=r"(r2), "=r"(r3) : "r"(addr));
}

__device__ __forceinline__ void mma_tf32(float c[4],
                                         uint32_t a0, uint32_t a1, uint32_t a2, uint32_t a3,
                                         uint32_t b0, uint32_t b1) {
    asm volatile(
        "mma.sync.aligned.m16n8k8.row.col.f32.tf32.tf32.f32 "
        "{%0,%1,%2,%3},{%4,%5,%6,%7},{%8,%9},{%0,%1,%2,%3};"
        : "+f"(c[0]), "+f"(c[1]), "+f"(c[2]), "+f"(c[3])
        : "r"(a0), "r"(a1), "r"(a2), "r"(a3), "r"(b0), "r"(b1));
}

__device__ __forceinline__ void cpa16(uint32_t s, const void* g) {
    asm volatile("cp.async.cg.shared.global [%0], [%1], 16;" :: "r"(s), "l"(g));
}

// ---------------------------------------------------------------------------
// Kernel 0: single fused tf32-rounding pass over hidden + 4 weights.
// ---------------------------------------------------------------------------
constexpr int HID4 = Mrows * Dc / 4;    // 786432
constexpr int W4   = Dc * Dc / 4;       // 147456
constexpr int CVT_TOT = HID4 + 4 * W4;  // 1376256

__global__ void cvt_all_kernel(const float4* __restrict__ hid,
                               const float4* __restrict__ wq,
                               const float4* __restrict__ wk,
                               const float4* __restrict__ wv,
                               const float4* __restrict__ wo) {
    const int i = blockIdx.x * blockDim.x + threadIdx.x;
    if (i >= CVT_TOT) return;
    const float4* src;
    float4* dst;
    int off;
    if (i < HID4) {
        src = hid; dst = (float4*)g_hid_tf; off = i;
    } else {
        const int j = i - HID4;
        const int w = j / W4;
        off = j - w * W4;
        src = (w == 0) ? wq : (w == 1) ? wk : (w == 2) ? wv : wo;
        dst = (w < 3) ? (float4*)g_w_tf + (size_t)w * W4 : (float4*)g_wo_tf;
    }
    float4 v = src[off];
    float4 r;
    r.x = __uint_as_float(f2tf(v.x));
    r.y = __uint_as_float(f2tf(v.y));
    r.z = __uint_as_float(f2tf(v.z));
    r.w = __uint_as_float(f2tf(v.w));
    dst[off] = r;
}

// ---------------------------------------------------------------------------
// Kernel 1: tf32 GEMM (identical to R13 known-good).
// ---------------------------------------------------------------------------
constexpr int GLD = 36;                        // smem row pitch (floats), 144B
constexpr int GEMM_SMEM = 2 * (128 + 256) * GLD * 4;   // 110592 B

template<int MODE>
__global__ __launch_bounds__(512, 1)
void gemm_tf32_kernel(float* __restrict__ Cout,
                      const float* __restrict__ cosp,
                      const float* __restrict__ sinp) {
    extern __shared__ uint32_t sm[];
    uint32_t* As = sm;                          // [2][128*GLD]
    uint32_t* Bs = sm + 2 * 128 * GLD;          // [2][256*GLD]

    const int tid = threadIdx.x;
    const int warp = tid >> 5, lane = tid & 31;
    const int gr = lane >> 2, gc = lane & 3;
    const int m0 = blockIdx.y * 128;
    const int n0g = blockIdx.x * 256;

    const float* Arow = ((MODE == 1) ? g_hid_tf : g_o) + (size_t)m0 * Dc;
    const float* Brow = ((MODE == 1) ? g_w_tf : g_wo_tf) + (size_t)n0g * Dc;

    const int warp_m0 = (warp >> 2) * 32;       // 4 warps in m
    const int warp_n0 = (warp & 3) * 64;        // 4 warps in n

    const uint32_t laneA = ((lane & 15) * GLD + 4 * (lane >> 4)) * 4;
    const uint32_t laneB = ((((lane >> 3) & 1) * 8 + (lane & 7)) * GLD) * 4
                         + (lane >> 4) * 16;
    const uint32_t AsU = s2u(As), BsU = s2u(Bs);

    auto load_tile = [&](int kt, int buf) {
        uint32_t Ab = AsU + buf * 128 * GLD * 4;
        uint32_t Bb = BsU + buf * 256 * GLD * 4;
#pragma unroll
        for (int i = 0; i < 2; i++) {            // A: 128 rows x 8 chunks
            const int idx = tid + i * 512;
            const int r = idx >> 3;
            const int cB = (idx & 7) << 4;
            cpa16(Ab + r * GLD * 4 + cB, Arow + (size_t)r * Dc + kt * 32 + (cB >> 2));
        }
#pragma unroll
        for (int i = 0; i < 4; i++) {            // B: 256 rows x 8 chunks
            const int idx = tid + i * 512;
            const int r = idx >> 3;
            const int cB = (idx & 7) << 4;
            cpa16(Bb + r * GLD * 4 + cB, Brow + (size_t)r * Dc + kt * 32 + (cB >> 2));
        }
        asm volatile("cp.async.commit_group;");
    };

    float c[2][8][4] = {};                       // [mt][nt][frag]

    load_tile(0, 0);

    for (int kt = 0; kt < 24; kt++) {
        const int buf = kt & 1;
        if (kt < 23) {
            load_tile(kt + 1, buf ^ 1);
            asm volatile("cp.async.wait_group 1;");
        } else {
            asm volatile("cp.async.wait_group 0;");
        }
        __syncthreads();

        const uint32_t AbU = AsU + buf * 128 * GLD * 4;
        const uint32_t BbU = BsU + buf * 256 * GLD * 4;
#pragma unroll
        for (int kk = 0; kk < 4; kk++) {
            const int klo = kk * 8;
            uint32_t a[2][4], bf[4][4];
#pragma unroll
            for (int mt = 0; mt < 2; mt++)
                lm4(a[mt][0], a[mt][1], a[mt][2], a[mt][3],
                    AbU + ((warp_m0 + mt * 16) * GLD + klo) * 4 + laneA);
#pragma unroll
            for (int g = 0; g < 4; g++)
                lm4(bf[g][0], bf[g][1], bf[g][2], bf[g][3],
                    BbU + ((warp_n0 + g * 16) * GLD + klo) * 4 + laneB);
#pragma unroll
            for (int mt = 0; mt < 2; mt++)
#pragma unroll
                for (int nt = 0; nt < 8; nt++) {
                    const int g = nt >> 1, hf = nt & 1;
                    mma_tf32(c[mt][nt], a[mt][0], a[mt][1], a[mt][2], a[mt][3],
                             bf[g][hf], bf[g][2 + hf]);
                }
        }
        __syncthreads();
    }

    if (MODE == 0) {
#pragma unroll
        for (int mt = 0; mt < 2; mt++)
#pragma unroll
            for (int nt = 0; nt < 8; nt++) {
                const int row = m0 + warp_m0 + mt * 16 + gr;
                const int col = n0g + warp_n0 + nt * 8 + 2 * gc;
                Cout[(size_t)(row    ) * Dc + col    ] = c[mt][nt][0];
                Cout[(size_t)(row    ) * Dc + col + 1] = c[mt][nt][1];
                Cout[(size_t)(row + 8) * Dc + col    ] = c[mt][nt][2];
                Cout[(size_t)(row + 8) * Dc + col + 1] = c[mt][nt][3];
            }
    } else {
        const int which = n0g / Dc;              // 256-tiles never straddle
        const int n0 = n0g % Dc;
        if (which < 2) {
            // ---- fused SiLU + RoPE for q/k ----
            float* dst = which ? g_k : g_q;
            float* cosS = (float*)sm;            // [128][68]
            float* sinS = cosS + 128 * 68;
#pragma unroll
            for (int i = 0; i < 4; i++) {
                const int idx = tid + i * 512;   // 2048 float4
                const int r = idx >> 4;
                const int c4 = (idx & 15) << 2;
                *(float4*)&cosS[r * 68 + c4] =
                    *(const float4*)&cosp[(size_t)(m0 + r) * HDc + c4];
                *(float4*)&sinS[r * 68 + c4] =
                    *(const float4*)&sinp[(size_t)(m0 + r) * HDc + c4];
            }
            __syncthreads();
            const int h = (n0 + warp_n0) >> 6;
#pragma unroll
            for (int mt = 0; mt < 2; mt++)
#pragma unroll
                for (int half = 0; half < 2; half++)
#pragma unroll
                    for (int nt = 0; nt < 4; nt++)
#pragma unroll
                        for (int e = 0; e < 2; e++) {
                            const int r = warp_m0 + mt * 16 + half * 8 + gr;
                            const int d = nt * 8 + 2 * gc + e;
                            const float x1 = silu_f(c[mt][nt    ][half * 2 + e]);
                            const float x2 = silu_f(c[mt][nt + 4][half * 2 + e]);
                            const float c1 = cosS[r * 68 + d];
                            const float s1 = sinS[r * 68 + d];
                            const float c2 = cosS[r * 68 + d + 32];
                            const float s2 = sinS[r * 68 + d + 32];
                            const int m = m0 + r, b = m >> 11, l = m & 2047;
                            const size_t base = (((size_t)b * Hc + h) * Lc + l) * HDc;
                            dst[base + d] =
                                __uint_as_float(f2tf(x1 * c1 - x2 * s1));
                            dst[base + d + 32] =
                                __uint_as_float(f2tf(x2 * c2 + x1 * s2));
                        }
        } else {
            // ---- v: SiLU only ----
#pragma unroll
            for (int mt = 0; mt < 2; mt++)
#pragma unroll
                for (int nt = 0; nt < 8; nt++)
#pragma unroll
                    for (int half = 0; half < 2; half++)
#pragma unroll
                        for (int e = 0; e < 2; e++) {
                            const int row = m0 + warp_m0 + mt * 16 + half * 8 + gr;
                            const int colL = n0 + warp_n0 + nt * 8 + 2 * gc + e;
                            const int hh = colL >> 6, d = colL & 63;
                            const int b = row >> 11, l = row & 2047;
                            g_v[(((size_t)b * Hc + hh) * Lc + l) * HDc + d] =
                                __uint_as_float(f2tf(silu_f(c[mt][nt][half * 2 + e])));
                        }
        }
    }
}

// ---------------------------------------------------------------------------
// Kernel 2: causal attention, mma.sync tf32. 128-row q tiles x 128-wide
// k-tiles (2 syncs per 128 k-cols instead of 4). Kb double-buffered cp.async,
// Vb single-buffered (reload issued after mid sync, covered by SV compute).
// QK computed in two 64-col halves to cap registers.
// ---------------------------------------------------------------------------
constexpr int AKP = 68;                   // Kb/Vb row pitch (words)
constexpr int ASP = 132;                  // Ss/Vt row pitch (words)
constexpr int OFF_KB = 0;                 // [2][128][AKP]
constexpr int OFF_VB = 2 * 128 * AKP;     // [128][AKP]
constexpr int OFF_VT = OFF_VB + 128 * AKP;        // [64][ASP]
constexpr int OFF_SS = OFF_VT + 64 * ASP;         // [128][ASP]
constexpr int ATTN_SMEM = (OFF_SS + 128 * ASP) * 4;   // 205824 B
constexpr int QTILES = Lc / 128;          // 16

__global__ __launch_bounds__(512, 1)
void attn_mma_kernel(float* __restrict__ attn_out) {
    extern __shared__ uint32_t sm[];
    uint32_t* Vb = sm + OFF_VB;
    uint32_t* Vt = sm + OFF_VT;
    float*    Ss = (float*)(sm + OFF_SS);

    const int tid = threadIdx.x;
    const int warp = tid >> 5, lane = tid & 31;
    const int gr = lane >> 2, gc = lane & 3;
    const int qt = QTILES - 1 - (int)blockIdx.x / BH;
    const int bh = (int)blockIdx.x % BH;
    const int q0 = qt * 128;

    const int warp_m0 = (warp >> 1) * 16;   // 8 warps in m (q rows)
    const int warp_n0 = (warp & 1) * 32;    // 2 warps in n

    const uint32_t laneAS = ((lane & 15) * ASP + 4 * (lane >> 4)) * 4;       // Ss A-frags
    const uint32_t laneBK = ((((lane >> 3) & 1) * 8 + (lane & 7)) * AKP) * 4
                          + (lane >> 4) * 16;                                 // Kb B-frags
    const uint32_t laneBV = ((((lane >> 3) & 1) * 8 + (lane & 7)) * ASP) * 4
                          + (lane >> 4) * 16;                                 // Vt B-frags
    const uint32_t KbU = s2u(sm + OFF_KB), VtU = s2u(Vt), SsU = s2u(Ss);
    const uint32_t VbU = s2u(Vb);

    const float* Qg = g_q + (size_t)bh * Lc * HDc;
    const float* Kg = g_k + (size_t)bh * Lc * HDc;
    const float* Vg = g_v + (size_t)bh * Lc * HDc;
    float* attn_base = attn_out + (size_t)bh * Lc * Lc;

    // K tile: 128 rows x 64 floats = 2048 16B chunks -> 4/thread.
    auto load_k = [&](int kt, int buf) {
        const uint32_t kB = KbU + buf * 128 * AKP * 4;
#pragma unroll
        for (int i = 0; i < 4; i++) {
            const int idx = tid + i * 512;
            const int r = idx >> 4;
            const int cB = (idx & 15) << 4;
            cpa16(kB + r * AKP * 4 + cB, Kg + (size_t)(kt * 128 + r) * HDc + (cB >> 2));
        }
        asm volatile("cp.async.commit_group;");
    };
    auto load_v = [&](int kt) {
#pragma unroll
        for (int i = 0; i < 4; i++) {
            const int idx = tid + i * 512;
            const int r = idx >> 4;
            const int cB = (idx & 15) << 4;
            cpa16(VbU + r * AKP * 4 + cB, Vg + (size_t)(kt * 128 + r) * HDc + (cB >> 2));
        }
        asm volatile("cp.async.commit_group;");
    };

    load_k(0, 0);
    load_v(0);

    // Stage Q into Ss, preload Q fragments.
#pragma unroll
    for (int i = 0; i < 4; i++) {
        const int idx = tid + i * 512;
        const int r = idx >> 4;
        const int c4 = (idx & 15) << 2;
        *(float4*)&Ss[r * ASP + c4] = *(const float4*)&Qg[(size_t)(q0 + r) * HDc + c4];
    }
    __syncthreads();

    uint32_t qf[8][4];
#pragma unroll
    for (int kk = 0; kk < 8; kk++)
        lm4(qf[kk][0], qf[kk][1], qf[kk][2], qf[kk][3],
            SsU + (warp_m0 * ASP + kk * 8) * 4 + laneAS);

    float o[4][4] = {};
    const int ktn = qt + 1;                 // 128-wide k tiles

    for (int kt = 0; kt < ktn; kt++) {
        const int cur = kt & 1;
        asm volatile("cp.async.wait_group 0;");
        __syncthreads();        // Kb[cur]+Vb ready; prev SV reads of Vt/Ss done

        if (kt + 1 < ktn) load_k(kt + 1, cur ^ 1);

        // Transpose Vb -> Vt[d][k] (full 128 k-cols).
        {
            const int d = tid & 63;
            const int rg = tid >> 6;        // 0..7, k block rg*16
            uint32_t t[16];
#pragma unroll
            for (int j = 0; j < 16; j++) t[j] = Vb[(rg * 16 + j) * AKP + d];
#pragma unroll
            for (int j4 = 0; j4 < 16; j4 += 4)
                *(uint4*)&Vt[d * ASP + rg * 16 + j4] = *(uint4*)&t[j4];
        }

        // S = Q K^T, two 64-col halves (caps registers at s[4][4]).
        const uint32_t kBU = KbU + cur * 128 * AKP * 4;
#pragma unroll
        for (int h = 0; h < 2; h++) {
            float s[4][4] = {};
#pragma unroll
            for (int kk = 0; kk < 8; kk++) {
                uint32_t bf[2][4];
#pragma unroll
                for (int g = 0; g < 2; g++)
                    lm4(bf[g][0], bf[g][1], bf[g][2], bf[g][3],
                        kBU + ((h * 64 + warp_n0 + g * 16) * AKP + kk * 8) * 4 + laneBK);
#pragma unroll
                for (int nt = 0; nt < 4; nt++) {
                    const int g = nt >> 1, hf = nt & 1;
                    mma_tf32(s[nt], qf[kk][0], qf[kk][1], qf[kk][2], qf[kk][3],
                             bf[g][hf], bf[g][2 + hf]);
                }
            }
            // mask + silu/L -> Ss cols h*64..
#pragma unroll
            for (int nt = 0; nt < 4; nt++)
#pragma unroll
                for (int half = 0; half < 2; half++)
#pragma unroll
                    for (int e = 0; e < 2; e++) {
                        const int row = warp_m0 + half * 8 + gr;
                        const int col = h * 64 + warp_n0 + nt * 8 + 2 * gc + e;
                        const int q = q0 + row;
                        const int k = kt * 128 + col;
                        const float x = s[nt][half * 2 + e];
                        Ss[row * ASP + col] =
                            (k <= q) ? silu_fast(x) * (1.0f / Lc) : 0.0f;
                    }
        }
        __syncthreads();        // Vt + Ss ready; Vb fully consumed

        if (kt + 1 < ktn) load_v(kt + 1);

        // attn gmem write: 128x128 floats -> 8 float4/thread
#pragma unroll
        for (int i = 0; i < 8; i++) {
            const int idx = tid + i * 512;
            const int r = idx >> 5;
            const int c4 = (idx & 31) << 2;
            *(float4*)&attn_base[(size_t)(q0 + r) * Lc + kt * 128 + c4] =
                *(const float4*)&Ss[r * ASP + c4];
        }

        // O += S @ V  (16 kk over 128 k-cols)
#pragma unroll
        for (int kk = 0; kk < 16; kk++) {
            const int klo = kk * 8;
            uint32_t a[4], bf[2][4];
            lm4(a[0], a[1], a[2], a[3],
                SsU + (warp_m0 * ASP + klo) * 4 + laneAS);
#pragma unroll
            for (int j = 0; j < 4; j++)
                a[j] = f2tf(__uint_as_float(a[j]));
#pragma unroll
            for (int g = 0; g < 2; g++)
                lm4(bf[g][0], bf[g][1], bf[g][2], bf[g][3],
                    VtU + ((warp_n0 + g * 16) * ASP + klo) * 4 + laneBV);
#pragma unroll
            for (int nt = 0; nt < 4; nt++) {
                const int g = nt >> 1, hf = nt & 1;
                mma_tf32(o[nt], a[0], a[1], a[2], a[3], bf[g][hf], bf[g][2 + hf]);
            }
        }
    }

    // Zero-fill strictly-upper region (k >= q0+128)
    const int zstart = q0 + 128;
    const int zcols = Lc - zstart;
    if (zcols > 0) {
        const int row4 = zcols >> 2;
        const int tot4 = 128 * row4;
        for (int e = tid; e < tot4; e += 512) {
            const int row = e / row4;
            const int c4 = (e % row4) << 2;
            *(float4*)&attn_base[(size_t)(q0 + row) * Lc + zstart + c4] =
                make_float4(0.f, 0.f, 0.f, 0.f);
        }
    }

    // Write O (tf32-rounded, feeds cp.async output projection)
    const int b = bh / Hc;
    const int h = bh % Hc;
#pragma unroll
    for (int nt = 0; nt < 4; nt++)
#pragma unroll
        for (int half = 0; half < 2; half++)
#pragma unroll
            for (int e = 0; e < 2; e++) {
                const int row = q0 + warp_m0 + half * 8 + gr;
                const int d = warp_n0 + nt * 8 + 2 * gc + e;
                g_o[((size_t)b * Lc + row) * Dc + h * HDc + d] =
                    __uint_as_float(f2tf(o[nt][half * 2 + e]));
            }
}

// ---------------------------------------------------------------------------
// Launch. Inputs: hidden_states, attention_mask, cos, sin, Wq, Wk, Wv, Wo.
// Output: [attn_output (B*L*D) | attn (B*H*L*L)]. Mask handled analytically.
// ---------------------------------------------------------------------------
extern "C" void kernel_launch(void* const* d_in, const int* in_sizes, int n_in,
                              void* d_out, int out_size) {
    const float* hidden = (const float*)d_in[0];
    const float* cosp   = (const float*)d_in[2];
    const float* sinp   = (const float*)d_in[3];
    const float* Wq     = (const float*)d_in[4];
    const float* Wk     = (const float*)d_in[5];
    const float* Wv     = (const float*)d_in[6];
    const float* Wo     = (const float*)d_in[7];

    float* out = (float*)d_out;
    float* attn_out = out + (size_t)Bc * Lc * Dc;

    cudaFuncSetAttribute(gemm_tf32_kernel<1>,
                         cudaFuncAttributeMaxDynamicSharedMemorySize, GEMM_SMEM);
    cudaFuncSetAttribute(gemm_tf32_kernel<0>,
                         cudaFuncAttributeMaxDynamicSharedMemorySize, GEMM_SMEM);
    cudaFuncSetAttribute(attn_mma_kernel,
                         cudaFuncAttributeMaxDynamicSharedMemorySize, ATTN_SMEM);

    // 0) One fused tf32-rounding pass (hidden + all weights).
    cvt_all_kernel<<<(CVT_TOT + 255) / 256, 256>>>(
        (const float4*)hidden, (const float4*)Wq, (const float4*)Wk,
        (const float4*)Wv, (const float4*)Wo);

    // 1) QKV projections + SiLU + fused RoPE (128x256 tiles)
    gemm_tf32_kernel<1><<<dim3(3 * Dc / 256, Mrows / 128), 512, GEMM_SMEM>>>(
        nullptr, cosp, sinp);

    // 2) Attention (128-wide k tiles, qt-descending schedule)
    attn_mma_kernel<<<QTILES * BH, 512, ATTN_SMEM>>>(attn_out);

    // 3) Output projection (128x256 tiles — as R13)
    gemm_tf32_kernel<0><<<dim3(Dc / 256, Mrows / 128), 512, GEMM_SMEM>>>(
        out, nullptr, nullptr);
}

// round 17
// speedup vs baseline: 1.6658x; 1.0722x over previous
#include <cuda_runtime.h>
#include <cuda_bf16.h>
#include <cstdint>

// Problem constants
constexpr int Bc  = 2;
constexpr int Lc  = 2048;
constexpr int Dc  = 768;
constexpr int Hc  = 12;
constexpr int HDc = 64;
constexpr int BH  = Bc * Hc;            // 24
constexpr int Mrows = Bc * Lc;          // 4096

// Scratch (device globals; no allocation allowed)
__device__ __align__(128) float g_q[(size_t)BH * Lc * HDc];   // [b,h,l,d] tf32 (post-RoPE)
__device__ __align__(128) float g_k[(size_t)BH * Lc * HDc];
__device__ __align__(128) float g_v[(size_t)BH * Lc * HDc];
__device__ __align__(128) float g_o[(size_t)Bc * Lc * Dc];    // [b,l,h*64+d] tf32
__device__ __align__(128) float g_hid_tf[(size_t)Mrows * Dc];
__device__ __align__(128) float g_w_tf[(size_t)3 * Dc * Dc];
__device__ __align__(128) float g_wo_tf[(size_t)Dc * Dc];

__device__ __forceinline__ float silu_f(float x) {
    return x / (1.0f + __expf(-x));
}

// Fast SiLU: 2 MUFU + 2 FMA, flag-independent, rel err ~1e-6.
__device__ __forceinline__ float silu_fast(float x) {
    float e, r;
    asm("ex2.approx.f32 %0, %1;" : "=f"(e) : "f"(-x * 1.4426950408889634f));
    asm("rcp.approx.f32 %0, %1;" : "=f"(r) : "f"(1.0f + e));
    return x * r;
}

__device__ __forceinline__ uint32_t f2tf(float x) {
    uint32_t r;
    asm("cvt.rna.tf32.f32 %0, %1;" : "=r"(r) : "f"(x));
    return r;
}

__device__ __forceinline__ uint32_t s2u(const void* p) {
    return (uint32_t)__cvta_generic_to_shared(p);
}

__device__ __forceinline__ void lm4(uint32_t& r0, uint32_t& r1,
                                    uint32_t& r2, uint32_t& r3, uint32_t addr) {
    asm volatile("ldmatrix.sync.aligned.m8n8.x4.shared.b16 {%0,%1,%2,%3},[%4];"
                 : "=r"(r0), "=r"(r1), "=r"(r2), "=r"(r3) : "r"(addr));
}

__device__ __forceinline__ void mma_tf32(float c[4],
                                         uint32_t a0, uint32_t a1, uint32_t a2, uint32_t a3,
                                         uint32_t b0, uint32_t b1) {
    asm volatile(
        "mma.sync.aligned.m16n8k8.row.col.f32.tf32.tf32.f32 "
        "{%0,%1,%2,%3},{%4,%5,%6,%7},{%8,%9},{%0,%1,%2,%3};"
        : "+f"(c[0]), "+f"(c[1]), "+f"(c[2]), "+f"(c[3])
        : "r"(a0), "r"(a1), "r"(a2), "r"(a3), "r"(b0), "r"(b1));
}

__device__ __forceinline__ void cpa16(uint32_t s, const void* g) {
    asm volatile("cp.async.cg.shared.global [%0], [%1], 16;" :: "r"(s), "l"(g));
}

// ---------------------------------------------------------------------------
// Kernel 0: single fused tf32-rounding pass over hidden + 4 weights.
// 2 float4 per thread.
// ---------------------------------------------------------------------------
constexpr int HID4 = Mrows * Dc / 4;    // 786432
constexpr int W4   = Dc * Dc / 4;       // 147456
constexpr int CVT_TOT = HID4 + 4 * W4;  // 1376256

__global__ void cvt_all_kernel(const float4* __restrict__ hid,
                               const float4* __restrict__ wq,
                               const float4* __restrict__ wk,
                               const float4* __restrict__ wv,
                               const float4* __restrict__ wo) {
    const int base = (blockIdx.x * blockDim.x + threadIdx.x) * 2;
#pragma unroll
    for (int u = 0; u < 2; u++) {
        const int i = base + u;
        if (i >= CVT_TOT) return;
        const float4* src;
        float4* dst;
        int off;
        if (i < HID4) {
            src = hid; dst = (float4*)g_hid_tf; off = i;
        } else {
            const int j = i - HID4;
            const int w = j / W4;
            off = j - w * W4;
            src = (w == 0) ? wq : (w == 1) ? wk : (w == 2) ? wv : wo;
            dst = (w < 3) ? (float4*)g_w_tf + (size_t)w * W4 : (float4*)g_wo_tf;
        }
        float4 v = src[off];
        float4 r;
        r.x = __uint_as_float(f2tf(v.x));
        r.y = __uint_as_float(f2tf(v.y));
        r.z = __uint_as_float(f2tf(v.z));
        r.w = __uint_as_float(f2tf(v.w));
        dst[off] = r;
    }
}

// ---------------------------------------------------------------------------
// Kernel 1: tf32 GEMM (identical to R14 known-good).
// ---------------------------------------------------------------------------
constexpr int GLD = 36;                        // smem row pitch (floats), 144B
constexpr int GEMM_SMEM = 2 * (128 + 256) * GLD * 4;   // 110592 B

template<int MODE>
__global__ __launch_bounds__(512, 1)
void gemm_tf32_kernel(float* __restrict__ Cout,
                      const float* __restrict__ cosp,
                      const float* __restrict__ sinp) {
    extern __shared__ uint32_t sm[];
    uint32_t* As = sm;                          // [2][128*GLD]
    uint32_t* Bs = sm + 2 * 128 * GLD;          // [2][256*GLD]

    const int tid = threadIdx.x;
    const int warp = tid >> 5, lane = tid & 31;
    const int gr = lane >> 2, gc = lane & 3;
    const int m0 = blockIdx.y * 128;
    const int n0g = blockIdx.x * 256;

    const float* Arow = ((MODE == 1) ? g_hid_tf : g_o) + (size_t)m0 * Dc;
    const float* Brow = ((MODE == 1) ? g_w_tf : g_wo_tf) + (size_t)n0g * Dc;

    const int warp_m0 = (warp >> 2) * 32;       // 4 warps in m
    const int warp_n0 = (warp & 3) * 64;        // 4 warps in n

    const uint32_t laneA = ((lane & 15) * GLD + 4 * (lane >> 4)) * 4;
    const uint32_t laneB = ((((lane >> 3) & 1) * 8 + (lane & 7)) * GLD) * 4
                         + (lane >> 4) * 16;
    const uint32_t AsU = s2u(As), BsU = s2u(Bs);

    auto load_tile = [&](int kt, int buf) {
        uint32_t Ab = AsU + buf * 128 * GLD * 4;
        uint32_t Bb = BsU + buf * 256 * GLD * 4;
#pragma unroll
        for (int i = 0; i < 2; i++) {            // A: 128 rows x 8 chunks
            const int idx = tid + i * 512;
            const int r = idx >> 3;
            const int cB = (idx & 7) << 4;
            cpa16(Ab + r * GLD * 4 + cB, Arow + (size_t)r * Dc + kt * 32 + (cB >> 2));
        }
#pragma unroll
        for (int i = 0; i < 4; i++) {            // B: 256 rows x 8 chunks
            const int idx = tid + i * 512;
            const int r = idx >> 3;
            const int cB = (idx & 7) << 4;
            cpa16(Bb + r * GLD * 4 + cB, Brow + (size_t)r * Dc + kt * 32 + (cB >> 2));
        }
        asm volatile("cp.async.commit_group;");
    };

    float c[2][8][4] = {};                       // [mt][nt][frag]

    load_tile(0, 0);

    for (int kt = 0; kt < 24; kt++) {
        const int buf = kt & 1;
        if (kt < 23) {
            load_tile(kt + 1, buf ^ 1);
            asm volatile("cp.async.wait_group 1;");
        } else {
            asm volatile("cp.async.wait_group 0;");
        }
        __syncthreads();

        const uint32_t AbU = AsU + buf * 128 * GLD * 4;
        const uint32_t BbU = BsU + buf * 256 * GLD * 4;
#pragma unroll
        for (int kk = 0; kk < 4; kk++) {
            const int klo = kk * 8;
            uint32_t a[2][4], bf[4][4];
#pragma unroll
            for (int mt = 0; mt < 2; mt++)
                lm4(a[mt][0], a[mt][1], a[mt][2], a[mt][3],
                    AbU + ((warp_m0 + mt * 16) * GLD + klo) * 4 + laneA);
#pragma unroll
            for (int g = 0; g < 4; g++)
                lm4(bf[g][0], bf[g][1], bf[g][2], bf[g][3],
                    BbU + ((warp_n0 + g * 16) * GLD + klo) * 4 + laneB);
#pragma unroll
            for (int mt = 0; mt < 2; mt++)
#pragma unroll
                for (int nt = 0; nt < 8; nt++) {
                    const int g = nt >> 1, hf = nt & 1;
                    mma_tf32(c[mt][nt], a[mt][0], a[mt][1], a[mt][2], a[mt][3],
                             bf[g][hf], bf[g][2 + hf]);
                }
        }
        __syncthreads();
    }

    if (MODE == 0) {
#pragma unroll
        for (int mt = 0; mt < 2; mt++)
#pragma unroll
            for (int nt = 0; nt < 8; nt++) {
                const int row = m0 + warp_m0 + mt * 16 + gr;
                const int col = n0g + warp_n0 + nt * 8 + 2 * gc;
                Cout[(size_t)(row    ) * Dc + col    ] = c[mt][nt][0];
                Cout[(size_t)(row    ) * Dc + col + 1] = c[mt][nt][1];
                Cout[(size_t)(row + 8) * Dc + col    ] = c[mt][nt][2];
                Cout[(size_t)(row + 8) * Dc + col + 1] = c[mt][nt][3];
            }
    } else {
        const int which = n0g / Dc;              // 256-tiles never straddle
        const int n0 = n0g % Dc;
        if (which < 2) {
            // ---- fused SiLU + RoPE for q/k ----
            float* dst = which ? g_k : g_q;
            float* cosS = (float*)sm;            // [128][68]
            float* sinS = cosS + 128 * 68;
#pragma unroll
            for (int i = 0; i < 4; i++) {
                const int idx = tid + i * 512;   // 2048 float4
                const int r = idx >> 4;
                const int c4 = (idx & 15) << 2;
                *(float4*)&cosS[r * 68 + c4] =
                    *(const float4*)&cosp[(size_t)(m0 + r) * HDc + c4];
                *(float4*)&sinS[r * 68 + c4] =
                    *(const float4*)&sinp[(size_t)(m0 + r) * HDc + c4];
            }
            __syncthreads();
            const int h = (n0 + warp_n0) >> 6;
#pragma unroll
            for (int mt = 0; mt < 2; mt++)
#pragma unroll
                for (int half = 0; half < 2; half++)
#pragma unroll
                    for (int nt = 0; nt < 4; nt++)
#pragma unroll
                        for (int e = 0; e < 2; e++) {
                            const int r = warp_m0 + mt * 16 + half * 8 + gr;
                            const int d = nt * 8 + 2 * gc + e;
                            const float x1 = silu_f(c[mt][nt    ][half * 2 + e]);
                            const float x2 = silu_f(c[mt][nt + 4][half * 2 + e]);
                            const float c1 = cosS[r * 68 + d];
                            const float s1 = sinS[r * 68 + d];
                            const float c2 = cosS[r * 68 + d + 32];
                            const float s2 = sinS[r * 68 + d + 32];
                            const int m = m0 + r, b = m >> 11, l = m & 2047;
                            const size_t base = (((size_t)b * Hc + h) * Lc + l) * HDc;
                            dst[base + d] =
                                __uint_as_float(f2tf(x1 * c1 - x2 * s1));
                            dst[base + d + 32] =
                                __uint_as_float(f2tf(x2 * c2 + x1 * s2));
                        }
        } else {
            // ---- v: SiLU only ----
#pragma unroll
            for (int mt = 0; mt < 2; mt++)
#pragma unroll
                for (int nt = 0; nt < 8; nt++)
#pragma unroll
                    for (int half = 0; half < 2; half++)
#pragma unroll
                        for (int e = 0; e < 2; e++) {
                            const int row = m0 + warp_m0 + mt * 16 + half * 8 + gr;
                            const int colL = n0 + warp_n0 + nt * 8 + 2 * gc + e;
                            const int hh = colL >> 6, d = colL & 63;
                            const int b = row >> 11, l = row & 2047;
                            g_v[(((size_t)b * Hc + hh) * Lc + l) * HDc + d] =
                                __uint_as_float(f2tf(silu_f(c[mt][nt][half * 2 + e])));
                        }
        }
    }
}

// ---------------------------------------------------------------------------
// Kernel 2: causal attention, mma.sync tf32. 128x128 k-tiles, Kb double-
// buffered cp.async, Vb single-buffered. SV A-frags fed raw (HW tf32
// truncation) — no cvt in SV loop. STG after SV MMAs. Diagonal-only masking.
// ---------------------------------------------------------------------------
constexpr int AKP = 68;                   // Kb/Vb row pitch (words)
constexpr int ASP = 132;                  // Ss/Vt row pitch (words)
constexpr int OFF_KB = 0;                 // [2][128][AKP]
constexpr int OFF_VB = 2 * 128 * AKP;     // [128][AKP]
constexpr int OFF_VT = OFF_VB + 128 * AKP;        // [64][ASP]
constexpr int OFF_SS = OFF_VT + 64 * ASP;         // [128][ASP]
constexpr int ATTN_SMEM = (OFF_SS + 128 * ASP) * 4;   // 205824 B
constexpr int QTILES = Lc / 128;          // 16

__global__ __launch_bounds__(512, 1)
void attn_mma_kernel(float* __restrict__ attn_out) {
    extern __shared__ uint32_t sm[];
    uint32_t* Vb = sm + OFF_VB;
    uint32_t* Vt = sm + OFF_VT;
    float*    Ss = (float*)(sm + OFF_SS);

    const int tid = threadIdx.x;
    const int warp = tid >> 5, lane = tid & 31;
    const int gr = lane >> 2, gc = lane & 3;
    const int qt = QTILES - 1 - (int)blockIdx.x / BH;
    const int bh = (int)blockIdx.x % BH;
    const int q0 = qt * 128;

    const int warp_m0 = (warp >> 1) * 16;   // 8 warps in m (q rows)
    const int warp_n0 = (warp & 1) * 32;    // 2 warps in n

    const uint32_t laneAS = ((lane & 15) * ASP + 4 * (lane >> 4)) * 4;       // Ss A-frags
    const uint32_t laneBK = ((((lane >> 3) & 1) * 8 + (lane & 7)) * AKP) * 4
                          + (lane >> 4) * 16;                                 // Kb B-frags
    const uint32_t laneBV = ((((lane >> 3) & 1) * 8 + (lane & 7)) * ASP) * 4
                          + (lane >> 4) * 16;                                 // Vt B-frags
    const uint32_t KbU = s2u(sm + OFF_KB), VtU = s2u(Vt), SsU = s2u(Ss);
    const uint32_t VbU = s2u(Vb);

    const float* Qg = g_q + (size_t)bh * Lc * HDc;
    const float* Kg = g_k + (size_t)bh * Lc * HDc;
    const float* Vg = g_v + (size_t)bh * Lc * HDc;
    float* attn_base = attn_out + (size_t)bh * Lc * Lc;

    auto load_k = [&](int kt, int buf) {
        const uint32_t kB = KbU + buf * 128 * AKP * 4;
#pragma unroll
        for (int i = 0; i < 4; i++) {
            const int idx = tid + i * 512;
            const int r = idx >> 4;
            const int cB = (idx & 15) << 4;
            cpa16(kB + r * AKP * 4 + cB, Kg + (size_t)(kt * 128 + r) * HDc + (cB >> 2));
        }
        asm volatile("cp.async.commit_group;");
    };
    auto load_v = [&](int kt) {
#pragma unroll
        for (int i = 0; i < 4; i++) {
            const int idx = tid + i * 512;
            const int r = idx >> 4;
            const int cB = (idx & 15) << 4;
            cpa16(VbU + r * AKP * 4 + cB, Vg + (size_t)(kt * 128 + r) * HDc + (cB >> 2));
        }
        asm volatile("cp.async.commit_group;");
    };

    load_k(0, 0);
    load_v(0);

    // Stage Q into Ss, preload Q fragments.
#pragma unroll
    for (int i = 0; i < 4; i++) {
        const int idx = tid + i * 512;
        const int r = idx >> 4;
        const int c4 = (idx & 15) << 2;
        *(float4*)&Ss[r * ASP + c4] = *(const float4*)&Qg[(size_t)(q0 + r) * HDc + c4];
    }
    __syncthreads();

    uint32_t qf[8][4];
#pragma unroll
    for (int kk = 0; kk < 8; kk++)
        lm4(qf[kk][0], qf[kk][1], qf[kk][2], qf[kk][3],
            SsU + (warp_m0 * ASP + kk * 8) * 4 + laneAS);

    float o[4][4] = {};
    const int ktn = qt + 1;                 // 128-wide k tiles

    for (int kt = 0; kt < ktn; kt++) {
        const int cur = kt & 1;
        const bool diag = (kt == qt);
        asm volatile("cp.async.wait_group 0;");
        __syncthreads();        // Kb[cur]+Vb ready; prev SV reads of Vt/Ss done

        if (kt + 1 < ktn) load_k(kt + 1, cur ^ 1);

        // Transpose Vb -> Vt[d][k] (full 128 k-cols).
        {
            const int d = tid & 63;
            const int rg = tid >> 6;        // 0..7, k block rg*16
            uint32_t t[16];
#pragma unroll
            for (int j = 0; j < 16; j++) t[j] = Vb[(rg * 16 + j) * AKP + d];
#pragma unroll
            for (int j4 = 0; j4 < 16; j4 += 4)
                *(uint4*)&Vt[d * ASP + rg * 16 + j4] = *(uint4*)&t[j4];
        }

        // S = Q K^T, two 64-col halves (caps registers at s[4][4]).
        const uint32_t kBU = KbU + cur * 128 * AKP * 4;
#pragma unroll
        for (int h = 0; h < 2; h++) {
            float s[4][4] = {};
#pragma unroll
            for (int kk = 0; kk < 8; kk++) {
                uint32_t bf[2][4];
#pragma unroll
                for (int g = 0; g < 2; g++)
                    lm4(bf[g][0], bf[g][1], bf[g][2], bf[g][3],
                        kBU + ((h * 64 + warp_n0 + g * 16) * AKP + kk * 8) * 4 + laneBK);
#pragma unroll
                for (int nt = 0; nt < 4; nt++) {
                    const int g = nt >> 1, hf = nt & 1;
                    mma_tf32(s[nt], qf[kk][0], qf[kk][1], qf[kk][2], qf[kk][3],
                             bf[g][hf], bf[g][2 + hf]);
                }
            }
            // silu/L (+mask on diagonal tile only) -> Ss cols h*64..
            if (!diag) {
#pragma unroll
                for (int nt = 0; nt < 4; nt++)
#pragma unroll
                    for (int half = 0; half < 2; half++)
#pragma unroll
                        for (int e = 0; e < 2; e++) {
                            const int row = warp_m0 + half * 8 + gr;
                            const int col = h * 64 + warp_n0 + nt * 8 + 2 * gc + e;
                            Ss[row * ASP + col] =
                                silu_fast(s[nt][half * 2 + e]) * (1.0f / Lc);
                        }
            } else {
#pragma unroll
                for (int nt = 0; nt < 4; nt++)
#pragma unroll
                    for (int half = 0; half < 2; half++)
#pragma unroll
                        for (int e = 0; e < 2; e++) {
                            const int row = warp_m0 + half * 8 + gr;
                            const int col = h * 64 + warp_n0 + nt * 8 + 2 * gc + e;
                            const float x = s[nt][half * 2 + e];
                            Ss[row * ASP + col] =
                                (col <= row) ? silu_fast(x) * (1.0f / Lc) : 0.0f;
                        }
            }
        }
        __syncthreads();        // Vt + Ss ready; Vb fully consumed

        if (kt + 1 < ktn) load_v(kt + 1);

        // O += S @ V  (16 kk over 128 k-cols; raw fp32 A-frags, HW truncates)
#pragma unroll
        for (int kk = 0; kk < 16; kk++) {
            const int klo = kk * 8;
            uint32_t a[4], bf[2][4];
            lm4(a[0], a[1], a[2], a[3],
                SsU + (warp_m0 * ASP + klo) * 4 + laneAS);
#pragma unroll
            for (int g = 0; g < 2; g++)
                lm4(bf[g][0], bf[g][1], bf[g][2], bf[g][3],
                    VtU + ((warp_n0 + g * 16) * ASP + klo) * 4 + laneBV);
#pragma unroll
            for (int nt = 0; nt < 4; nt++) {
                const int g = nt >> 1, hf = nt & 1;
                mma_tf32(o[nt], a[0], a[1], a[2], a[3], bf[g][hf], bf[g][2 + hf]);
            }
        }

        // attn gmem write (after MMAs; drains before next barrier)
#pragma unroll
        for (int i = 0; i < 8; i++) {
            const int idx = tid + i * 512;
            const int r = idx >> 5;
            const int c4 = (idx & 31) << 2;
            *(float4*)&attn_base[(size_t)(q0 + r) * Lc + kt * 128 + c4] =
                *(const float4*)&Ss[r * ASP + c4];
        }
    }

    // Zero-fill strictly-upper region (k >= q0+128)
    const int zstart = q0 + 128;
    const int zcols = Lc - zstart;
    if (zcols > 0) {
        const int row4 = zcols >> 2;
        const int tot4 = 128 * row4;
        for (int e = tid; e < tot4; e += 512) {
            const int row = e / row4;
            const int c4 = (e % row4) << 2;
            *(float4*)&attn_base[(size_t)(q0 + row) * Lc + zstart + c4] =
                make_float4(0.f, 0.f, 0.f, 0.f);
        }
    }

    // Write O (tf32-rounded, feeds cp.async output projection)
    const int b = bh / Hc;
    const int h = bh % Hc;
#pragma unroll
    for (int nt = 0; nt < 4; nt++)
#pragma unroll
        for (int half = 0; half < 2; half++)
#pragma unroll
            for (int e = 0; e < 2; e++) {
                const int row = q0 + warp_m0 + half * 8 + gr;
                const int d = warp_n0 + nt * 8 + 2 * gc + e;
                g_o[((size_t)b * Lc + row) * Dc + h * HDc + d] =
                    __uint_as_float(f2tf(o[nt][half * 2 + e]));
            }
}

// ---------------------------------------------------------------------------
// Launch. Inputs: hidden_states, attention_mask, cos, sin, Wq, Wk, Wv, Wo.
// Output: [attn_output (B*L*D) | attn (B*H*L*L)]. Mask handled analytically.
// ---------------------------------------------------------------------------
extern "C" void kernel_launch(void* const* d_in, const int* in_sizes, int n_in,
                              void* d_out, int out_size) {
    const float* hidden = (const float*)d_in[0];
    const float* cosp   = (const float*)d_in[2];
    const float* sinp   = (const float*)d_in[3];
    const float* Wq     = (const float*)d_in[4];
    const float* Wk     = (const float*)d_in[5];
    const float* Wv     = (const float*)d_in[6];
    const float* Wo     = (const float*)d_in[7];

    float* out = (float*)d_out;
    float* attn_out = out + (size_t)Bc * Lc * Dc;

    cudaFuncSetAttribute(gemm_tf32_kernel<1>,
                         cudaFuncAttributeMaxDynamicSharedMemorySize, GEMM_SMEM);
    cudaFuncSetAttribute(gemm_tf32_kernel<0>,
                         cudaFuncAttributeMaxDynamicSharedMemorySize, GEMM_SMEM);
    cudaFuncSetAttribute(attn_mma_kernel,
                         cudaFuncAttributeMaxDynamicSharedMemorySize, ATTN_SMEM);

    // 0) One fused tf32-rounding pass (hidden + all weights).
    cvt_all_kernel<<<(CVT_TOT / 2 + 511) / 512, 512>>>(
        (const float4*)hidden, (const float4*)Wq, (const float4*)Wk,
        (const float4*)Wv, (const float4*)Wo);

    // 1) QKV projections + SiLU + fused RoPE (128x256 tiles)
    gemm_tf32_kernel<1><<<dim3(3 * Dc / 256, Mrows / 128), 512, GEMM_SMEM>>>(
        nullptr, cosp, sinp);

    // 2) Attention (128-wide k tiles, qt-descending schedule)
    attn_mma_kernel<<<QTILES * BH, 512, ATTN_SMEM>>>(attn_out);

    // 3) Output projection (128x256 tiles)
    gemm_tf32_kernel<0><<<dim3(Dc / 256, Mrows / 128), 512, GEMM_SMEM>>>(
        out, nullptr, nullptr);
}